// round 2
// baseline (speedup 1.0000x reference)
#include <cuda_runtime.h>

// ---------------------------------------------------------------------------
// KbModel: fisheye re-project. theta = AdamInverse(ru) is a pure scalar
// function of ru -> tabulate it once per launch (exact reference recurrence
// at 8193 grid nodes), then the main kernel is a memory-bound map with one
// 8-byte table gather + lerp per pixel.
// ---------------------------------------------------------------------------

#define TAB     8192
#define NSTEPS  100
#define RMAXF   1.21f

// packed table: g_tab2[i] = (T[i], T[i+1])  -> single aligned 8B gather + lerp
__device__ float2 g_tab2[TAB];

// ---------------------------------------------------------------------------
// Kernel 1: build T on the grid r_i = i * H, i = 0..TAB  (TAB+1 nodes).
// Runs the reference Adam recurrence faithfully in fp32.
// ---------------------------------------------------------------------------
__global__ void build_table_kernel(const float* __restrict__ kv, float n_elems)
{
    int i = blockIdx.x * blockDim.x + threadIdx.x;
    if (i > TAB) return;

    const float H = RMAXF / (float)(TAB - 1);
    float r = (float)i * H;

    float k0 = kv[0], k1 = kv[1], k2 = kv[2], k3 = kv[3], k4 = kv[4];
    float d1 = k1;
    float d2 = 2.0f * k2;
    float d3 = 3.0f * k3;
    float d4 = 4.0f * k4;

    const float scale = 2.0f / n_elems;   // MSE mean-reduction grad scale
    const float B1 = 0.9f, B2 = 0.999f, LR = 0.01f, EPS = 1e-8f;

    float theta = 0.0f, m = 0.0f, v = 0.0f;
    float p1 = 1.0f, p2 = 1.0f;           // B1^t, B2^t

    for (int t = 1; t <= NSTEPS; ++t) {
        p1 *= B1;
        p2 *= B2;
        // f(theta) and f'(theta) via Horner (0^0 == 1 handled naturally)
        float f  = fmaf(fmaf(fmaf(fmaf(k4, theta, k3), theta, k2), theta, k1), theta, k0);
        float fp = fmaf(fmaf(fmaf(d4, theta, d3), theta, d2), theta, d1);
        float g  = scale * (f - r) * fp;

        m = fmaf(B1, m, (1.0f - B1) * g);
        v = fmaf(B2, v, (1.0f - B2) * (g * g));

        float m_hat = m / (1.0f - p1);
        float v_hat = v / (1.0f - p2);
        theta = theta - LR * m_hat / (sqrtf(v_hat) + EPS);
    }

    // scatter into packed pair table: tab2[i] = (T_i, T_{i+1})
    if (i < TAB)  g_tab2[i].x     = theta;
    if (i >= 1)   g_tab2[i - 1].y = theta;
}

// ---------------------------------------------------------------------------
// Kernel 2: per-pixel map, 2 pixels per thread (float4 load/store).
//   mx,my = (p - C)/F ; ru = |(mx,my)| ; theta = lerp(T, ru)
//   th = atan2(|sin th|, cos th) == |theta|   (|theta| < pi/2 in range)
//   u = poly(th) * sin(theta) * mx/ru * F + C   (same for v)
// ---------------------------------------------------------------------------
__device__ __forceinline__ void map_one(float px, float py,
                                        float k0, float k1, float k2,
                                        float k3, float k4,
                                        float& u, float& v)
{
    const float INV_F = 1.0f / 600.0f;
    const float F     = 600.0f;
    const float CX    = 512.0f;
    const float CY    = 512.0f;
    const float INVH  = (float)(TAB - 1) / RMAXF;

    float mx = (px - CX) * INV_F;
    float my = (py - CY) * INV_F;

    float r2  = fmaf(mx, mx, my * my);
    float inv = rsqrtf(r2);          // 1/ru
    float ru  = r2 * inv;            // ru

    // table lookup + lerp
    float tt = ru * INVH;
    tt = fminf(tt, (float)(TAB - 1) - 1e-3f);   // keep ti <= TAB-2
    int   ti = (int)tt;
    float w  = tt - (float)ti;
    float2 e = g_tab2[ti];
    float theta = fmaf(w, e.y - e.x, e.x);

    float s = __sinf(theta);
    float X = s * mx * inv;          // pts.x = sin(theta) * mx / ru
    float Y = s * my * inv;

    float th = fabsf(theta);         // == atan2(|sin|, cos) for |theta| < pi/2

    float d = fmaf(fmaf(fmaf(fmaf(k4, th, k3), th, k2), th, k1), th, k0);

    u = fmaf(d * X, F, CX);
    v = fmaf(d * Y, F, CY);
}

__global__ void __launch_bounds__(256)
forward_kernel(const float4* __restrict__ in,
               const float*  __restrict__ kv,
               float4*       __restrict__ out,
               int n4,   // number of float4 groups (= 2-pixel groups)
               int n)    // number of pixels
{
    int idx = blockIdx.x * blockDim.x + threadIdx.x;
    if (idx >= n4) return;

    float k0 = kv[0], k1 = kv[1], k2 = kv[2], k3 = kv[3], k4 = kv[4];

    float4 p = in[idx];
    float4 o;

    map_one(p.x, p.y, k0, k1, k2, k3, k4, o.x, o.y);

    if (2 * idx + 1 < n) {
        map_one(p.z, p.w, k0, k1, k2, k3, k4, o.z, o.w);
    } else {
        o.z = 0.0f; o.w = 0.0f;
    }

    out[idx] = o;
}

// ---------------------------------------------------------------------------
extern "C" void kernel_launch(void* const* d_in, const int* in_sizes, int n_in,
                              void* d_out, int out_size)
{
    const float* inp = (const float*)d_in[0];   // (N,2) float32 pixels
    const float* kv  = (const float*)d_in[1];   // 5 float32 coeffs
    int n  = in_sizes[0] / 2;                   // number of pixels
    int n4 = (n + 1) / 2;                       // 2 pixels per float4

    build_table_kernel<<<(TAB + 1 + 127) / 128, 128>>>(kv, (float)n);

    int threads = 256;
    int blocks  = (n4 + threads - 1) / threads;
    forward_kernel<<<blocks, threads>>>((const float4*)inp, kv,
                                        (float4*)d_out, n4, n);
}

// round 4
// speedup vs baseline: 1.3208x; 1.3208x over previous
#include <cuda_runtime.h>

// ---------------------------------------------------------------------------
// KbModel fisheye re-project.
//  K1: tabulate theta = AdamInverse(r) on 2049 nodes (exact reference Adam
//      recurrence; latency-bound dependent chain, ~70 cyc/iter after the
//      __fdividef rewrite).
//  K2: streaming map, table held in SMEM (random gathers were L1-wavefront
//      bound when served from L1tex: R2 ncu showed L1=46.9% > DRAM=23.6%).
// ---------------------------------------------------------------------------

#define TAB     2048
#define NSTEPS  100
#define RMAXF   1.21f

// packed table: g_tab2[i] = (T[i], T[i+1])  -> one aligned 8B gather + lerp
__device__ float2 g_tab2[TAB];

// ---------------------------------------------------------------------------
// Kernel 1: build T on grid r_i = i*H, i = 0..TAB.
// ---------------------------------------------------------------------------
__global__ void build_table_kernel(const float* __restrict__ kv, float n_elems)
{
    int i = blockIdx.x * blockDim.x + threadIdx.x;
    if (i > TAB) return;

    const float H = RMAXF / (float)(TAB - 1);
    float r = (float)i * H;

    float k0 = kv[0], k1 = kv[1], k2 = kv[2], k3 = kv[3], k4 = kv[4];
    float d1 = k1;
    float d2 = 2.0f * k2;
    float d3 = 3.0f * k3;
    float d4 = 4.0f * k4;

    const float scale = 2.0f / n_elems;   // MSE mean-reduction grad scale
    const float B1 = 0.9f, B2 = 0.999f, LR = 0.01f, EPS = 1e-8f;

    float theta = 0.0f, m = 0.0f, v = 0.0f;
    float p1 = 1.0f, p2 = 1.0f;           // B1^t, B2^t (independent chain)

    #pragma unroll 4
    for (int t = 1; t <= NSTEPS; ++t) {
        p1 *= B1;
        p2 *= B2;
        float f  = fmaf(fmaf(fmaf(fmaf(k4, theta, k3), theta, k2), theta, k1), theta, k0);
        float fp = fmaf(fmaf(fmaf(d4, theta, d3), theta, d2), theta, d1);
        float g  = scale * (f - r) * fp;

        m = fmaf(B1, m, (1.0f - B1) * g);
        v = fmaf(B2, v, (1.0f - B2) * (g * g));

        // bias-correction divisors depend only on the p-chain -> their rcp
        // hoists off the critical path with __fdividef
        float m_hat = __fdividef(m, 1.0f - p1);
        float v_hat = __fdividef(v, 1.0f - p2);
        theta = theta - LR * __fdividef(m_hat, sqrtf(v_hat) + EPS);
    }

    if (i < TAB)  g_tab2[i].x     = theta;
    if (i >= 1)   g_tab2[i - 1].y = theta;
}

// ---------------------------------------------------------------------------
// Kernel 2: per-pixel map, 2 pixels per thread (float4), SMEM table.
// ---------------------------------------------------------------------------
__device__ __forceinline__ void map_one(const float2* __restrict__ s_tab,
                                        float px, float py,
                                        float k0, float k1, float k2,
                                        float k3, float k4,
                                        float& u, float& v)
{
    const float INV_F = 1.0f / 600.0f;
    const float F     = 600.0f;
    const float CX    = 512.0f;
    const float CY    = 512.0f;
    const float INVH  = (float)(TAB - 1) / RMAXF;

    float mx = (px - CX) * INV_F;
    float my = (py - CY) * INV_F;

    float r2  = fmaf(mx, mx, my * my);
    float inv = rsqrtf(r2);          // 1/ru
    float ru  = r2 * inv;            // ru

    float tt = ru * INVH;
    tt = fminf(tt, (float)(TAB - 1) - 1e-3f);
    int   ti = (int)tt;
    float w  = tt - (float)ti;
    float2 e = s_tab[ti];
    float theta = fmaf(w, e.y - e.x, e.x);

    float s = __sinf(theta);
    float X = s * mx * inv;          // sin(theta) * mx / ru
    float Y = s * my * inv;

    float th = fabsf(theta);         // atan2(|sin|,cos) == |theta|, |theta|<pi/2

    float d = fmaf(fmaf(fmaf(fmaf(k4, th, k3), th, k2), th, k1), th, k0);

    u = fmaf(d * X, F, CX);
    v = fmaf(d * Y, F, CY);
}

__global__ void __launch_bounds__(256)
forward_kernel(const float4* __restrict__ in,
               const float*  __restrict__ kv,
               float4*       __restrict__ out,
               int n4, int n)
{
    __shared__ float2 s_tab[TAB];

    // cooperative table load: 16KB = 1024 float4
    {
        const float4* src = (const float4*)g_tab2;
        float4*       dst = (float4*)s_tab;
        for (int i = threadIdx.x; i < TAB / 2; i += 256)
            dst[i] = src[i];
    }
    float k0 = kv[0], k1 = kv[1], k2 = kv[2], k3 = kv[3], k4 = kv[4];
    __syncthreads();

    int stride = gridDim.x * blockDim.x;
    for (int idx = blockIdx.x * blockDim.x + threadIdx.x; idx < n4; idx += stride) {
        float4 p = in[idx];
        float4 o;
        map_one(s_tab, p.x, p.y, k0, k1, k2, k3, k4, o.x, o.y);
        if (2 * idx + 1 < n) {
            map_one(s_tab, p.z, p.w, k0, k1, k2, k3, k4, o.z, o.w);
        } else {
            o.z = 0.0f; o.w = 0.0f;
        }
        out[idx] = o;
    }
}

// ---------------------------------------------------------------------------
extern "C" void kernel_launch(void* const* d_in, const int* in_sizes, int n_in,
                              void* d_out, int out_size)
{
    const float* inp = (const float*)d_in[0];   // (N,2) float32 pixels
    const float* kv  = (const float*)d_in[1];   // 5 float32 coeffs
    int n  = in_sizes[0] / 2;
    int n4 = (n + 1) / 2;

    build_table_kernel<<<(TAB + 1 + 127) / 128, 128>>>(kv, (float)n);

    int blocks = 1184;                          // 148 SMs x 8 CTAs, grid-stride
    int needed = (n4 + 255) / 256;
    if (needed < blocks) blocks = needed;
    forward_kernel<<<blocks, 256>>>((const float4*)inp, kv,
                                    (float4*)d_out, n4, n);
}

// round 6
// speedup vs baseline: 1.4482x; 1.0965x over previous
#include <cuda_runtime.h>

// ---------------------------------------------------------------------------
// KbModel fisheye re-project.
//  K1: tabulate theta = AdamInverse(r) on 2049 nodes. Pure dependent-chain
//      latency problem; bias-correction rcp/rsqrt hoisted onto the
//      independent p-chain so only ONE sqrt + ONE rcp remain per iteration
//      on the theta critical path. Estrin for f, f'.
//  K2: streaming map, 2 px/thread (float4), table in SMEM.
// ---------------------------------------------------------------------------

#define TAB     2048
#define NSTEPS  100
#define RMAXF   1.21f

// packed table: g_tab2[i] = (T[i], T[i+1])  -> one aligned 8B gather + lerp
__device__ float2 g_tab2[TAB];

// ---------------------------------------------------------------------------
// Kernel 1: build T on grid r_i = i*H, i = 0..TAB.
// ---------------------------------------------------------------------------
__global__ void build_table_kernel(const float* __restrict__ kv, float n_elems)
{
    int i = blockIdx.x * blockDim.x + threadIdx.x;
    if (i > TAB) return;

    const float H = RMAXF / (float)(TAB - 1);
    float r = (float)i * H;

    float k0 = kv[0], k1 = kv[1], k2 = kv[2], k3 = kv[3], k4 = kv[4];
    float k0r = k0 - r;                   // fold target into constant term
    float d1 = k1;
    float d2 = 2.0f * k2;
    float d3 = 3.0f * k3;
    float d4 = 4.0f * k4;

    const float scale = 2.0f / n_elems;   // MSE mean-reduction grad scale
    const float B1 = 0.9f, B2 = 0.999f, LR = 0.01f, EPS = 1e-8f;
    const float C1 = 1.0f - B1;           // 0.1
    const float SQC2 = 0.0316227766016838f; // sqrt(1 - B2)

    float theta = 0.0f, m = 0.0f, v = 0.0f;
    float p1 = 1.0f, p2 = 1.0f;           // B1^t, B2^t (independent chain)

    #pragma unroll 4
    for (int t = 1; t <= NSTEPS; ++t) {
        // ---- independent p-chain: both MUFUs overlap the f/g computation
        p1 *= B1;
        p2 *= B2;
        float inv1 = __fdividef(LR, 1.0f - p1);   // LR / (1 - B1^t)
        float rs2  = rsqrtf(1.0f - p2);           // 1 / sqrt(1 - B2^t)

        // ---- f - r and f' via Estrin
        float t2 = theta * theta;
        float fA = fmaf(k1, theta, k0r);
        float fB = fmaf(k4, theta, k3);
        fB = fmaf(fB, theta, k2);
        float fr = fmaf(fB, t2, fA);              // f(theta) - r

        float pA = fmaf(d2, theta, d1);
        float pB = fmaf(d4, theta, d3);
        float fp = fmaf(pB, t2, pA);              // f'(theta)
        float sg = scale * fp;

        float g  = fr * sg;

        // m/v updates; v gets (1-B2)*g^2 via pre-scaled h = g*sqrt(1-B2)
        m = fmaf(B1, m, C1 * g);
        float h = g * SQC2;
        v = fmaf(B2, v, h * h);

        // denom = sqrt(v_hat) + eps = sqrt(v)*rsqrt(1-B2^t) + eps
        float denom = fmaf(sqrtf(v), rs2, EPS);
        float num   = m * inv1;                   // LR * m_hat
        theta -= __fdividef(num, denom);
    }

    if (i < TAB)  g_tab2[i].x     = theta;
    if (i >= 1)   g_tab2[i - 1].y = theta;
}

// ---------------------------------------------------------------------------
// Kernel 2: per-pixel map, 2 pixels per thread (float4), SMEM table.
// ---------------------------------------------------------------------------
__device__ __forceinline__ void map_one(const float2* __restrict__ s_tab,
                                        float px, float py,
                                        float k0, float k1, float k2,
                                        float k3, float k4,
                                        float& u, float& v)
{
    const float INV_F = 1.0f / 600.0f;
    const float F     = 600.0f;
    const float CX    = 512.0f;
    const float CY    = 512.0f;
    const float INVH  = (float)(TAB - 1) / RMAXF;

    float mx = (px - CX) * INV_F;
    float my = (py - CY) * INV_F;

    float r2  = fmaf(mx, mx, my * my);
    float inv = rsqrtf(r2);          // 1/ru
    float ru  = r2 * inv;            // ru

    float tt = ru * INVH;
    tt = fminf(tt, (float)(TAB - 1) - 1e-3f);
    int   ti = (int)tt;
    float w  = tt - (float)ti;
    float2 e = s_tab[ti];
    float theta = fmaf(w, e.y - e.x, e.x);

    float s = __sinf(theta);
    float X = s * mx * inv;          // sin(theta) * mx / ru
    float Y = s * my * inv;

    float th = fabsf(theta);         // atan2(|sin|,cos) == |theta|, |theta|<pi/2

    float d = fmaf(fmaf(fmaf(fmaf(k4, th, k3), th, k2), th, k1), th, k0);

    u = fmaf(d * X, F, CX);
    v = fmaf(d * Y, F, CY);
}

__global__ void __launch_bounds__(512)
forward_kernel(const float4* __restrict__ in,
               const float*  __restrict__ kv,
               float4*       __restrict__ out,
               int n4, int n)
{
    __shared__ float2 s_tab[TAB];

    // cooperative table load: 16KB = 1024 float4, 512 threads -> 2 iters
    {
        const float4* src = (const float4*)g_tab2;
        float4*       dst = (float4*)s_tab;
        for (int i = threadIdx.x; i < TAB / 2; i += 512)
            dst[i] = src[i];
    }
    float k0 = kv[0], k1 = kv[1], k2 = kv[2], k3 = kv[3], k4 = kv[4];
    __syncthreads();

    int stride = gridDim.x * blockDim.x;
    for (int idx = blockIdx.x * blockDim.x + threadIdx.x; idx < n4; idx += stride) {
        float4 p = in[idx];
        float4 o;
        map_one(s_tab, p.x, p.y, k0, k1, k2, k3, k4, o.x, o.y);
        if (2 * idx + 1 < n) {
            map_one(s_tab, p.z, p.w, k0, k1, k2, k3, k4, o.z, o.w);
            out[idx] = o;
        } else {
            ((float2*)out)[2 * idx] = make_float2(o.x, o.y);
        }
    }
}

// ---------------------------------------------------------------------------
extern "C" void kernel_launch(void* const* d_in, const int* in_sizes, int n_in,
                              void* d_out, int out_size)
{
    const float* inp = (const float*)d_in[0];   // (N,2) float32 pixels
    const float* kv  = (const float*)d_in[1];   // 5 float32 coeffs
    int n  = in_sizes[0] / 2;
    int n4 = (n + 1) / 2;

    build_table_kernel<<<(TAB + 1 + 127) / 128, 128>>>(kv, (float)n);

    int blocks = 592;                           // 148 SMs x 4 CTAs of 512thr
    int needed = (n4 + 511) / 512;
    if (needed < blocks) blocks = needed;
    forward_kernel<<<blocks, 512>>>((const float4*)inp, kv,
                                    (float4*)d_out, n4, n);
}